// round 6
// baseline (speedup 1.0000x reference)
#include <cuda_runtime.h>

// Problem constants (fixed by the reference)
#define BATCH 16384
#define DIM   2048
#define NUMCL 1000

#define THREADS   256           // 8 warps -> 8 rows per block
#define NBLOCKS   (BATCH / 8)   // 2048 blocks

// Fused-reduction state (allocation-free rule: __device__ globals).
__device__ float        g_accum  = 0.0f;
__device__ unsigned int g_ticket = 0;

struct f8 { float a0,a1,a2,a3,a4,a5,a6,a7; };

// 256-bit load, L2 evict_last: pin the 8 MB T_EMB working set in L2
// (reused ~16x; must not lose to the 256 MB streaming traffic).
__device__ __forceinline__ f8 ldg256_evict_last(const void* p) {
    f8 v;
    asm volatile("ld.global.nc.L2::evict_last.v8.b32 {%0,%1,%2,%3,%4,%5,%6,%7}, [%8];"
                 : "=f"(v.a0), "=f"(v.a1), "=f"(v.a2), "=f"(v.a3),
                   "=f"(v.a4), "=f"(v.a5), "=f"(v.a6), "=f"(v.a7)
                 : "l"(p));
    return v;
}

// 256-bit load, L2 evict_first: stream-once data, don't pollute L2.
__device__ __forceinline__ f8 ldg256_evict_first(const void* p) {
    f8 v;
    asm volatile("ld.global.nc.L2::evict_first.v8.b32 {%0,%1,%2,%3,%4,%5,%6,%7}, [%8];"
                 : "=f"(v.a0), "=f"(v.a1), "=f"(v.a2), "=f"(v.a3),
                   "=f"(v.a4), "=f"(v.a5), "=f"(v.a6), "=f"(v.a7)
                 : "l"(p));
    return v;
}

__device__ __forceinline__ float fma8_dot(const f8& x, const f8& y, float acc) {
    acc = fmaf(x.a0, y.a0, acc); acc = fmaf(x.a1, y.a1, acc);
    acc = fmaf(x.a2, y.a2, acc); acc = fmaf(x.a3, y.a3, acc);
    acc = fmaf(x.a4, y.a4, acc); acc = fmaf(x.a5, y.a5, acc);
    acc = fmaf(x.a6, y.a6, acc); acc = fmaf(x.a7, y.a7, acc);
    return acc;
}

// ---------------------------------------------------------------------------
// Single fused kernel: one warp per row, 256-bit loads.
// DIM=2048 floats = 256 x 32B chunks; 32 lanes -> 8 iters/lane.
// ---------------------------------------------------------------------------
__global__ __launch_bounds__(THREADS, 8)
void dnl_fused_kernel(const float* __restrict__ s_emb,
                      const float* __restrict__ t_emb,
                      const float* __restrict__ T_EMB,
                      const int*   __restrict__ labels,
                      float*       __restrict__ out)
{
    const int warp = threadIdx.x >> 5;                 // 0..7
    const int lane = threadIdx.x & 31;
    const int row  = blockIdx.x * 8 + warp;            // 0..16383

    const size_t row_off = (size_t)row * DIM;
    const float* s = s_emb + row_off;
    const float* t = t_emb + row_off;

    // labels are int32 (JAX x64-disabled downcasts the reference's int64).
    int lbl = labels[row];
    lbl = (lbl < 0) ? 0 : ((lbl >= NUMCL) ? (NUMCL - 1) : lbl);
    const float* c = T_EMB + (size_t)lbl * DIM;

    float dot = 0.f, ss = 0.f, tt = 0.f, cc = 0.f;

    // 8 iterations of 32 floats-per-lane-stride (8 floats per lane per iter)
    #pragma unroll
    for (int i = 0; i < 8; ++i) {
        const int off = (i * 32 + lane) * 8;           // float offset
        const f8 sv = ldg256_evict_first(s + off);
        const f8 tv = ldg256_evict_first(t + off);
        const f8 cv = ldg256_evict_last (c + off);
        dot = fma8_dot(sv, cv, dot);
        ss  = fma8_dot(sv, sv, ss);
        tt  = fma8_dot(tv, tv, tt);
        cc  = fma8_dot(cv, cv, cc);
    }

    // Warp tree-reduce the four accumulators
    #pragma unroll
    for (int off = 16; off > 0; off >>= 1) {
        dot += __shfl_xor_sync(0xFFFFFFFFu, dot, off);
        ss  += __shfl_xor_sync(0xFFFFFFFFu, ss,  off);
        tt  += __shfl_xor_sync(0xFFFFFFFFu, tt,  off);
        cc  += __shfl_xor_sync(0xFFFFFFFFu, cc,  off);
    }

    // Block-level: 8 per-row losses -> one sum
    __shared__ float sh_loss[8];
    if (lane == 0) {
        const float max_norm = fmaxf(sqrtf(ss), sqrtf(tt));
        sh_loss[warp] = 1.0f - dot / (sqrtf(cc) * max_norm);
    }
    __syncthreads();

    if (threadIdx.x == 0) {
        float bsum = sh_loss[0] + sh_loss[1] + sh_loss[2] + sh_loss[3]
                   + sh_loss[4] + sh_loss[5] + sh_loss[6] + sh_loss[7];
        atomicAdd(&g_accum, bsum);

        // Make the add visible before taking a ticket
        __threadfence();
        unsigned int rank = atomicInc(&g_ticket, NBLOCKS - 1);  // wraps to 0
        if (rank == NBLOCKS - 1) {
            float total = *(volatile float*)&g_accum;
            out[0] = total * (1.0f / (float)BATCH);   // ND_WEIGHT = 1
            g_accum = 0.0f;                           // reset for next replay
        }
    }
}

// ---------------------------------------------------------------------------
// kernel_launch: graph-capturable, allocation-free, single launch.
// Inputs (metadata order): s_emb f32[B*D], t_emb f32[B*D],
//                          T_EMB f32[NUMCL*D], labels i32[B]
// Output: f32 scalar
// ---------------------------------------------------------------------------
extern "C" void kernel_launch(void* const* d_in, const int* in_sizes, int n_in,
                              void* d_out, int out_size)
{
    const float* s_emb  = (const float*)d_in[0];
    const float* t_emb  = (const float*)d_in[1];
    const float* T_EMB  = (const float*)d_in[2];
    const int*   labels = (const int*)d_in[3];
    float* out = (float*)d_out;

    dnl_fused_kernel<<<NBLOCKS, THREADS>>>(s_emb, t_emb, T_EMB, labels, out);
}

// round 7
// speedup vs baseline: 1.0501x; 1.0501x over previous
#include <cuda_runtime.h>

// Problem constants (fixed by the reference)
#define BATCH 16384
#define DIM   2048
#define NUMCL 1000

#define THREADS   256           // 8 warps -> 8 rows per block
#define NBLOCKS   (BATCH / 8)   // 2048 blocks

// Fused-reduction state (allocation-free rule: __device__ globals).
__device__ float        g_accum  = 0.0f;
__device__ unsigned int g_ticket = 0;

__device__ __forceinline__ float dot4(const float4& x, const float4& y, float acc) {
    return fmaf(x.x, y.x, fmaf(x.y, y.y, fmaf(x.z, y.z, fmaf(x.w, y.w, acc))));
}

// ---------------------------------------------------------------------------
// Single fused kernel: one warp per row, float4 loads (the R4 sweet spot),
// with loads explicitly batched 2 iterations deep (6 float4 in flight/lane)
// to raise MLP, and __ldlu (last-use) on the stream-once s/t data.
// ---------------------------------------------------------------------------
__global__ __launch_bounds__(THREADS, 6)
void dnl_fused_kernel(const float* __restrict__ s_emb,
                      const float* __restrict__ t_emb,
                      const float* __restrict__ T_EMB,
                      const int*   __restrict__ labels,
                      float*       __restrict__ out)
{
    const int warp = threadIdx.x >> 5;                 // 0..7
    const int lane = threadIdx.x & 31;
    const int row  = blockIdx.x * 8 + warp;            // 0..16383

    const size_t row_off = (size_t)row * DIM;
    const float4* __restrict__ s = (const float4*)(s_emb + row_off);
    const float4* __restrict__ t = (const float4*)(t_emb + row_off);

    // labels are int32 (JAX x64-disabled downcasts the reference's int64).
    int lbl = labels[row];
    lbl = (lbl < 0) ? 0 : ((lbl >= NUMCL) ? (NUMCL - 1) : lbl);
    const float4* __restrict__ c = (const float4*)(T_EMB + (size_t)lbl * DIM);

    float dot = 0.f, ss = 0.f, tt = 0.f, cc = 0.f;

    // DIM/4 = 512 float4 per row, 32 lanes -> 16 per lane, processed 2 at a
    // time with all 6 loads issued before any FMA consumes them.
    #pragma unroll
    for (int i = 0; i < 8; ++i) {
        const int i0 = (2 * i)     * 32 + lane;
        const int i1 = (2 * i + 1) * 32 + lane;

        const float4 sv0 = __ldlu(&s[i0]);   // last-use: read exactly once
        const float4 tv0 = __ldlu(&t[i0]);
        const float4 cv0 = __ldg (&c[i0]);   // reused across rows: keep cached
        const float4 sv1 = __ldlu(&s[i1]);
        const float4 tv1 = __ldlu(&t[i1]);
        const float4 cv1 = __ldg (&c[i1]);

        dot = dot4(sv0, cv0, dot);
        ss  = dot4(sv0, sv0, ss);
        tt  = dot4(tv0, tv0, tt);
        cc  = dot4(cv0, cv0, cc);
        dot = dot4(sv1, cv1, dot);
        ss  = dot4(sv1, sv1, ss);
        tt  = dot4(tv1, tv1, tt);
        cc  = dot4(cv1, cv1, cc);
    }

    // Warp tree-reduce the four accumulators
    #pragma unroll
    for (int off = 16; off > 0; off >>= 1) {
        dot += __shfl_xor_sync(0xFFFFFFFFu, dot, off);
        ss  += __shfl_xor_sync(0xFFFFFFFFu, ss,  off);
        tt  += __shfl_xor_sync(0xFFFFFFFFu, tt,  off);
        cc  += __shfl_xor_sync(0xFFFFFFFFu, cc,  off);
    }

    // Block-level: 8 per-row losses -> one sum
    __shared__ float sh_loss[8];
    if (lane == 0) {
        const float max_norm = fmaxf(sqrtf(ss), sqrtf(tt));
        sh_loss[warp] = 1.0f - dot / (sqrtf(cc) * max_norm);
    }
    __syncthreads();

    if (threadIdx.x == 0) {
        float bsum = sh_loss[0] + sh_loss[1] + sh_loss[2] + sh_loss[3]
                   + sh_loss[4] + sh_loss[5] + sh_loss[6] + sh_loss[7];
        atomicAdd(&g_accum, bsum);

        // Make the add visible before taking a ticket
        __threadfence();
        unsigned int rank = atomicInc(&g_ticket, NBLOCKS - 1);  // wraps to 0
        if (rank == NBLOCKS - 1) {
            float total = *(volatile float*)&g_accum;
            out[0] = total * (1.0f / (float)BATCH);   // ND_WEIGHT = 1
            g_accum = 0.0f;                           // reset for next replay
        }
    }
}

// ---------------------------------------------------------------------------
// kernel_launch: graph-capturable, allocation-free, single launch.
// Inputs (metadata order): s_emb f32[B*D], t_emb f32[B*D],
//                          T_EMB f32[NUMCL*D], labels i32[B]
// Output: f32 scalar
// ---------------------------------------------------------------------------
extern "C" void kernel_launch(void* const* d_in, const int* in_sizes, int n_in,
                              void* d_out, int out_size)
{
    const float* s_emb  = (const float*)d_in[0];
    const float* t_emb  = (const float*)d_in[1];
    const float* T_EMB  = (const float*)d_in[2];
    const int*   labels = (const int*)d_in[3];
    float* out = (float*)d_out;

    dnl_fused_kernel<<<NBLOCKS, THREADS>>>(s_emb, t_emb, T_EMB, labels, out);
}

// round 8
// speedup vs baseline: 1.0942x; 1.0420x over previous
#include <cuda_runtime.h>

// Problem constants (fixed by the reference)
#define BATCH 16384
#define DIM   2048
#define NUMCL 1000

#define THREADS     256                   // 8 warps per block
#define ROWS_PER_W  2                     // uniform work per warp
#define NWARPS      (BATCH / ROWS_PER_W)  // 8192 warps
#define NBLOCKS     (NWARPS / 8)          // 1024 blocks -> ONE uniform wave

// Fused-reduction state (allocation-free rule: __device__ globals).
__device__ float        g_accum  = 0.0f;
__device__ unsigned int g_ticket = 0;

__device__ __forceinline__ float dot4(const float4& x, const float4& y, float acc) {
    return fmaf(x.x, y.x, fmaf(x.y, y.y, fmaf(x.z, y.z, fmaf(x.w, y.w, acc))));
}

// ---------------------------------------------------------------------------
// Single fused kernel: each warp processes exactly 2 rows (rows w and
// w + NWARPS), giving 8192 uniform warp-tasks = one full warp-wave on 148 SMs
// (no 1.73-wave tail quantization). Load pattern identical to the best (R4)
// kernel: float4, __ldcs on stream-once s/t, __ldg on L2-reused centers.
// ---------------------------------------------------------------------------
__global__ __launch_bounds__(THREADS, 8)
void dnl_fused_kernel(const float* __restrict__ s_emb,
                      const float* __restrict__ t_emb,
                      const float* __restrict__ T_EMB,
                      const int*   __restrict__ labels,
                      float*       __restrict__ out)
{
    const int warp  = threadIdx.x >> 5;                 // 0..7
    const int lane  = threadIdx.x & 31;
    const int gwarp = blockIdx.x * 8 + warp;            // 0..8191

    float warp_loss = 0.0f;

    #pragma unroll
    for (int r = 0; r < ROWS_PER_W; ++r) {
        const int row = gwarp + r * NWARPS;             // 0..16383

        const size_t row_off = (size_t)row * DIM;
        const float4* __restrict__ s = (const float4*)(s_emb + row_off);
        const float4* __restrict__ t = (const float4*)(t_emb + row_off);

        // labels are int32 (JAX x64-disabled downcasts the reference's int64).
        int lbl = labels[row];
        lbl = (lbl < 0) ? 0 : ((lbl >= NUMCL) ? (NUMCL - 1) : lbl);
        const float4* __restrict__ c = (const float4*)(T_EMB + (size_t)lbl * DIM);

        float dot = 0.f, ss = 0.f, tt = 0.f, cc = 0.f;

        // DIM/4 = 512 float4 per row, 32 lanes -> 16 per lane
        #pragma unroll
        for (int i = 0; i < 16; ++i) {
            const int idx = i * 32 + lane;
            const float4 sv = __ldcs(&s[idx]);   // streaming: evict-first
            const float4 tv = __ldcs(&t[idx]);   // streaming: evict-first
            const float4 cv = __ldg (&c[idx]);   // reused across rows
            dot = dot4(sv, cv, dot);
            ss  = dot4(sv, sv, ss);
            tt  = dot4(tv, tv, tt);
            cc  = dot4(cv, cv, cc);
        }

        // Warp tree-reduce the four accumulators
        #pragma unroll
        for (int off = 16; off > 0; off >>= 1) {
            dot += __shfl_xor_sync(0xFFFFFFFFu, dot, off);
            ss  += __shfl_xor_sync(0xFFFFFFFFu, ss,  off);
            tt  += __shfl_xor_sync(0xFFFFFFFFu, tt,  off);
            cc  += __shfl_xor_sync(0xFFFFFFFFu, cc,  off);
        }

        const float max_norm = fmaxf(sqrtf(ss), sqrtf(tt));
        warp_loss += 1.0f - dot / (sqrtf(cc) * max_norm);
    }

    // Block-level: 8 per-warp losses -> one sum
    __shared__ float sh_loss[8];
    if (lane == 0) sh_loss[warp] = warp_loss;
    __syncthreads();

    if (threadIdx.x == 0) {
        float bsum = sh_loss[0] + sh_loss[1] + sh_loss[2] + sh_loss[3]
                   + sh_loss[4] + sh_loss[5] + sh_loss[6] + sh_loss[7];
        atomicAdd(&g_accum, bsum);

        // Make the add visible before taking a ticket
        __threadfence();
        unsigned int rank = atomicInc(&g_ticket, NBLOCKS - 1);  // wraps to 0
        if (rank == NBLOCKS - 1) {
            float total = *(volatile float*)&g_accum;
            out[0] = total * (1.0f / (float)BATCH);   // ND_WEIGHT = 1
            g_accum = 0.0f;                           // reset for next replay
        }
    }
}

// ---------------------------------------------------------------------------
// kernel_launch: graph-capturable, allocation-free, single launch.
// Inputs (metadata order): s_emb f32[B*D], t_emb f32[B*D],
//                          T_EMB f32[NUMCL*D], labels i32[B]
// Output: f32 scalar
// ---------------------------------------------------------------------------
extern "C" void kernel_launch(void* const* d_in, const int* in_sizes, int n_in,
                              void* d_out, int out_size)
{
    const float* s_emb  = (const float*)d_in[0];
    const float* t_emb  = (const float*)d_in[1];
    const float* T_EMB  = (const float*)d_in[2];
    const int*   labels = (const int*)d_in[3];
    float* out = (float*)d_out;

    dnl_fused_kernel<<<NBLOCKS, THREADS>>>(s_emb, t_emb, T_EMB, labels, out);
}